// round 1
// baseline (speedup 1.0000x reference)
#include <cuda_runtime.h>
#include <math.h>

#define BB 256
#define INF 256
#define HH 256
#define LL 2
#define SS 128
#define NSTK (SS + 1)
#define KTOT 512          // IN + H concatenated GEMM K
#define NG 1024           // 4*H gates

// ---------------- scratch (no allocations allowed) ----------------
__device__ float g_XH0[BB * KTOT];   // [x | h_prev0]
__device__ float g_XH1[BB * KTOT];   // [h0 | h_prev1]
__device__ float g_G0[BB * NG];      // gates layer 0
__device__ float g_G1[BB * NG];      // gates layer 1
__device__ float g_Cp0[BB * HH];
__device__ float g_Cp1[BB * HH];
__device__ float g_H0[BB * HH];
__device__ float g_C0[BB * HH];
__device__ float g_H1[BB * HH];
__device__ float g_C1[BB * HH];

// ---------------- gather: densify prev state, build XH0 ----------------
__global__ void k_gather(const float* __restrict__ x,
                         const float* __restrict__ hs,
                         const float* __restrict__ cs,
                         const int* __restrict__ pos) {
    int b = blockIdx.x;
    int h = threadIdx.x;
    int s = pos[b];
    size_t idx = (((size_t)s * BB + b) * HH + h) * LL;
    float2 hv = *(const float2*)(hs + idx);
    float2 cv = *(const float2*)(cs + idx);
    g_XH0[b * KTOT + h]        = x[b * INF + h];
    g_XH0[b * KTOT + INF + h]  = hv.x;   // layer0 h_prev
    g_XH1[b * KTOT + INF + h]  = hv.y;   // layer1 h_prev
    g_Cp0[b * HH + h] = cv.x;
    g_Cp1[b * HH + h] = cv.y;
}

// ---------------- GEMM: gates = XH (256x512) @ [Wih|Whh]^T (1024x512) ----------------
// BM=32, BN=64, BK=32, 256 threads, 2x4 microtile -> grid (16, 8) = 128 CTAs
template <int LAYER>
__global__ void __launch_bounds__(256) k_gemm(const float* __restrict__ Wih,
                                              const float* __restrict__ Whh) {
    const float* __restrict__ A = LAYER ? g_XH1 : g_XH0;
    float* __restrict__ Cout    = LAYER ? g_G1 : g_G0;

    __shared__ float As[32][34];  // [k][m], padded (8B-aligned float2 rows)
    __shared__ float Bs[32][68];  // [k][n], padded (16B-aligned float4 rows)

    const int n0 = blockIdx.x * 64;
    const int m0 = blockIdx.y * 32;
    const int t  = threadIdx.x;
    const int tx = t & 15;        // 0..15 -> 4 cols each
    const int ty = t >> 4;        // 0..15 -> 2 rows each

    float acc00 = 0.f, acc01 = 0.f, acc02 = 0.f, acc03 = 0.f;
    float acc10 = 0.f, acc11 = 0.f, acc12 = 0.f, acc13 = 0.f;

    for (int k0 = 0; k0 < KTOT; k0 += 32) {
        // A tile: 32 rows x 32 cols = 256 float4, 1 per thread
        {
            int row = t >> 3;          // 0..31
            int c4  = (t & 7) * 4;     // 0..28
            float4 v = *(const float4*)(A + (size_t)(m0 + row) * KTOT + k0 + c4);
            As[c4 + 0][row] = v.x;
            As[c4 + 1][row] = v.y;
            As[c4 + 2][row] = v.z;
            As[c4 + 3][row] = v.w;
        }
        // B tile: 64 rows(n) x 32 cols(k) = 512 float4, 2 per thread
        const float* __restrict__ Wp = (k0 < INF) ? Wih : Whh;
        const int kcol = (k0 < INF) ? k0 : (k0 - INF);
#pragma unroll
        for (int e = 0; e < 2; e++) {
            int idx = t + e * 256;     // 0..511
            int row = idx >> 3;        // 0..63
            int c4  = (idx & 7) * 4;
            float4 v = *(const float4*)(Wp + (size_t)(n0 + row) * INF + kcol + c4);
            Bs[c4 + 0][row] = v.x;
            Bs[c4 + 1][row] = v.y;
            Bs[c4 + 2][row] = v.z;
            Bs[c4 + 3][row] = v.w;
        }
        __syncthreads();

#pragma unroll
        for (int kk = 0; kk < 32; kk++) {
            float2 av = *(const float2*)(&As[kk][ty * 2]);
            float4 bv = *(const float4*)(&Bs[kk][tx * 4]);
            acc00 += av.x * bv.x; acc01 += av.x * bv.y;
            acc02 += av.x * bv.z; acc03 += av.x * bv.w;
            acc10 += av.y * bv.x; acc11 += av.y * bv.y;
            acc12 += av.y * bv.z; acc13 += av.y * bv.w;
        }
        __syncthreads();
    }

    {
        int m = m0 + ty * 2;
        int n = n0 + tx * 4;
        *(float4*)(Cout + (size_t)m * NG + n)       = make_float4(acc00, acc01, acc02, acc03);
        *(float4*)(Cout + (size_t)(m + 1) * NG + n) = make_float4(acc10, acc11, acc12, acc13);
    }
}

// ---------------- activation ----------------
template <int LAYER>
__global__ void k_act(const float* __restrict__ bih, const float* __restrict__ bhh) {
    int b = blockIdx.x;
    int h = threadIdx.x;
    const float* __restrict__ g  = (LAYER ? g_G1 : g_G0) + (size_t)b * NG;
    const float* __restrict__ cp = LAYER ? g_Cp1 : g_Cp0;

    float gi = g[h]            + bih[h]            + bhh[h];
    float gf = g[HH + h]       + bih[HH + h]       + bhh[HH + h];
    float gc = g[2 * HH + h]   + bih[2 * HH + h]   + bhh[2 * HH + h];
    float go = g[3 * HH + h]   + bih[3 * HH + h]   + bhh[3 * HH + h];

    float si = 1.0f / (1.0f + expf(-gi));
    float sf = 1.0f / (1.0f + expf(-gf));
    float so = 1.0f / (1.0f + expf(-go));
    float c2 = sf * cp[b * HH + h] + si * tanhf(gc);
    float h2 = so * tanhf(c2);

    if (LAYER == 0) {
        g_H0[b * HH + h] = h2;
        g_C0[b * HH + h] = c2;
        g_XH1[b * KTOT + h] = h2;   // feed layer 1 GEMM input
    } else {
        g_H1[b * HH + h] = h2;
        g_C1[b * HH + h] = c2;
    }
}

// ---------------- scatter new row + compute h_out/c_out ----------------
__global__ void k_scatter(const float* __restrict__ hs_in,
                          const float* __restrict__ cs_in,
                          const int* __restrict__ op,
                          const int* __restrict__ pos,
                          float* __restrict__ out) {
    float* __restrict__ h_out  = out;                 // (1,B,L)
    float* __restrict__ c_out  = out + BB * LL;       // (1,B,L)
    float* __restrict__ hs_out = out + 2 * BB * LL;
    float* __restrict__ cs_out = hs_out + (size_t)NSTK * BB * HH * LL;

    int b = blockIdx.x;
    int h = threadIdx.x;
    int p = pos[b];

    size_t base = (((size_t)(p + 1) * BB + b) * HH + h) * LL;
    float h0 = g_H0[b * HH + h], h1 = g_H1[b * HH + h];
    float c0 = g_C0[b * HH + h], c1 = g_C1[b * HH + h];
    *(float2*)(hs_out + base) = make_float2(h0, h1);
    *(float2*)(cs_out + base) = make_float2(c0, c1);

    if (h == 0) {
        int o  = op[b];
        int np = p + o;
        float2 hv, cv;
        if (o == 1) {
            hv = make_float2(g_H0[b * HH + (HH - 1)], g_H1[b * HH + (HH - 1)]);
            cv = make_float2(g_C0[b * HH + (HH - 1)], g_C1[b * HH + (HH - 1)]);
        } else {
            size_t gi = (((size_t)np * BB + b) * HH + (HH - 1)) * LL;
            hv = *(const float2*)(hs_in + gi);
            cv = *(const float2*)(cs_in + gi);
        }
        *(float2*)(h_out + b * LL) = hv;
        *(float2*)(c_out + b * LL) = cv;
    }
}

// ---------------- launch ----------------
extern "C" void kernel_launch(void* const* d_in, const int* in_sizes, int n_in,
                              void* d_out, int out_size) {
    const float* x    = (const float*)d_in[0];
    const float* hs   = (const float*)d_in[1];
    const float* cs   = (const float*)d_in[2];
    const float* wih0 = (const float*)d_in[3];
    const float* whh0 = (const float*)d_in[4];
    const float* bih0 = (const float*)d_in[5];
    const float* bhh0 = (const float*)d_in[6];
    const float* wih1 = (const float*)d_in[7];
    const float* whh1 = (const float*)d_in[8];
    const float* bih1 = (const float*)d_in[9];
    const float* bhh1 = (const float*)d_in[10];
    const int*   op   = (const int*)d_in[11];
    const int*   pos  = (const int*)d_in[12];
    float* out = (float*)d_out;

    const size_t stackN = (size_t)NSTK * BB * HH * LL;
    float* hs_out = out + 2 * BB * LL;
    float* cs_out = hs_out + stackN;

    // Bulk stack copy (dominant HBM traffic) — issued first.
    cudaMemcpyAsync(hs_out, hs, stackN * sizeof(float), cudaMemcpyDeviceToDevice);
    cudaMemcpyAsync(cs_out, cs, stackN * sizeof(float), cudaMemcpyDeviceToDevice);

    dim3 ggrid(NG / 64, BB / 32);  // (16, 8)

    k_gather<<<BB, HH>>>(x, hs, cs, pos);
    k_gemm<0><<<ggrid, 256>>>(wih0, whh0);
    k_act<0><<<BB, HH>>>(bih0, bhh0);
    k_gemm<1><<<ggrid, 256>>>(wih1, whh1);
    k_act<1><<<BB, HH>>>(bih1, bhh1);
    k_scatter<<<BB, HH>>>(hs, cs, op, pos, out);
}

// round 2
// speedup vs baseline: 1.0044x; 1.0044x over previous
#include <cuda_runtime.h>
#include <math.h>

#define BB 256
#define INF 256
#define HH 256
#define LL 2
#define SS 128
#define NSTK (SS + 1)
#define KTOT 512          // IN + H concatenated GEMM K
#define NG 1024           // 4*H gates

#define GEMM_CTAS 64      // (1024/64) * (256/64)
#define COPY_CTAS 232
#define STACKN ((size_t)NSTK * BB * HH * LL)   // 16,908,288 floats per stack

// ---------------- scratch (no allocations allowed) ----------------
__device__ float g_XH0[BB * KTOT];   // [x | h_prev0]
__device__ float g_XH1[BB * KTOT];   // [h0 | h_prev1]
__device__ float g_G0[BB * NG];      // gates layer 0
__device__ float g_G1[BB * NG];      // gates layer 1
__device__ float g_Cp0[BB * HH];
__device__ float g_Cp1[BB * HH];
__device__ float g_H0[BB * HH];
__device__ float g_C0[BB * HH];
__device__ float g_H1[BB * HH];
__device__ float g_C1[BB * HH];

// ---------------- gather: densify prev state, build XH0 ----------------
__global__ void k_gather(const float* __restrict__ x,
                         const float* __restrict__ hs,
                         const float* __restrict__ cs,
                         const int* __restrict__ pos) {
    int b = blockIdx.x;
    int h = threadIdx.x;
    int s = pos[b];
    size_t idx = (((size_t)s * BB + b) * HH + h) * LL;
    float2 hv = *(const float2*)(hs + idx);
    float2 cv = *(const float2*)(cs + idx);
    g_XH0[b * KTOT + h]        = x[b * INF + h];
    g_XH0[b * KTOT + INF + h]  = hv.x;   // layer0 h_prev
    g_XH1[b * KTOT + INF + h]  = hv.y;   // layer1 h_prev
    g_Cp0[b * HH + h] = cv.x;
    g_Cp1[b * HH + h] = cv.y;
}

// ---------------- fused GEMM + bulk stack copy ----------------
// GEMM: gates = XH (256x512) @ [Wih|Whh]^T (1024x512)
// bids [0, GEMM_CTAS): 64x64 tile, BK=16, 256 thr, 4x4 microtile
// bids [GEMM_CTAS, GEMM_CTAS+COPY_CTAS): float4 grid-stride copy of one stack
template <int LAYER>
__global__ void __launch_bounds__(256) k_gemm_copy(const float* __restrict__ Wih,
                                                   const float* __restrict__ Whh,
                                                   const float* __restrict__ copy_src,
                                                   float* __restrict__ copy_dst) {
    const int bid = blockIdx.x;
    const int t   = threadIdx.x;

    if (bid >= GEMM_CTAS) {
        // ---- copy role ----
        const float4* __restrict__ src = (const float4*)copy_src;
        float4* __restrict__ dst = (float4*)copy_dst;
        const size_t n4 = STACKN / 4;            // 4,227,072
        size_t i = (size_t)(bid - GEMM_CTAS) * 256 + t;
        const size_t stride = (size_t)COPY_CTAS * 256;
        for (; i < n4; i += stride) dst[i] = src[i];
        return;
    }

    // ---- GEMM role ----
    const float* __restrict__ A = LAYER ? g_XH1 : g_XH0;
    float* __restrict__ Cout    = LAYER ? g_G1 : g_G0;

    __shared__ float As[16][68];  // [k][m]
    __shared__ float Bs[16][68];  // [k][n]

    const int n0 = (bid & 15) * 64;   // 16 n-tiles
    const int m0 = (bid >> 4) * 64;   // 4 m-tiles
    const int tx = t & 15;            // n: 4 cols each
    const int ty = t >> 4;            // m: 4 rows each

    float acc[4][4];
#pragma unroll
    for (int i = 0; i < 4; i++)
#pragma unroll
        for (int j = 0; j < 4; j++) acc[i][j] = 0.f;

    const int lrow = t >> 2;          // 0..63
    const int lc4  = (t & 3) * 4;     // 0,4,8,12

    for (int k0 = 0; k0 < KTOT; k0 += 16) {
        // A tile: 64 rows x 16 k = 256 float4, 1/thread
        {
            float4 v = *(const float4*)(A + (size_t)(m0 + lrow) * KTOT + k0 + lc4);
            As[lc4 + 0][lrow] = v.x;
            As[lc4 + 1][lrow] = v.y;
            As[lc4 + 2][lrow] = v.z;
            As[lc4 + 3][lrow] = v.w;
        }
        // B tile: 64 n-rows x 16 k = 256 float4, 1/thread
        {
            const float* __restrict__ Wp = (k0 < INF) ? Wih : Whh;
            const int kcol = (k0 < INF) ? k0 : (k0 - INF);
            float4 v = *(const float4*)(Wp + (size_t)(n0 + lrow) * INF + kcol + lc4);
            Bs[lc4 + 0][lrow] = v.x;
            Bs[lc4 + 1][lrow] = v.y;
            Bs[lc4 + 2][lrow] = v.z;
            Bs[lc4 + 3][lrow] = v.w;
        }
        __syncthreads();

#pragma unroll
        for (int kk = 0; kk < 16; kk++) {
            float4 av = *(const float4*)(&As[kk][ty * 4]);
            float4 bv = *(const float4*)(&Bs[kk][tx * 4]);
            acc[0][0] += av.x * bv.x; acc[0][1] += av.x * bv.y;
            acc[0][2] += av.x * bv.z; acc[0][3] += av.x * bv.w;
            acc[1][0] += av.y * bv.x; acc[1][1] += av.y * bv.y;
            acc[1][2] += av.y * bv.z; acc[1][3] += av.y * bv.w;
            acc[2][0] += av.z * bv.x; acc[2][1] += av.z * bv.y;
            acc[2][2] += av.z * bv.z; acc[2][3] += av.z * bv.w;
            acc[3][0] += av.w * bv.x; acc[3][1] += av.w * bv.y;
            acc[3][2] += av.w * bv.z; acc[3][3] += av.w * bv.w;
        }
        __syncthreads();
    }

#pragma unroll
    for (int i = 0; i < 4; i++) {
        int m = m0 + ty * 4 + i;
        int n = n0 + tx * 4;
        *(float4*)(Cout + (size_t)m * NG + n) =
            make_float4(acc[i][0], acc[i][1], acc[i][2], acc[i][3]);
    }
}

// ---------------- activation ----------------
template <int LAYER>
__global__ void k_act(const float* __restrict__ bih, const float* __restrict__ bhh) {
    int b = blockIdx.x;
    int h = threadIdx.x;
    const float* __restrict__ g  = (LAYER ? g_G1 : g_G0) + (size_t)b * NG;
    const float* __restrict__ cp = LAYER ? g_Cp1 : g_Cp0;

    float gi = g[h]            + bih[h]            + bhh[h];
    float gf = g[HH + h]       + bih[HH + h]       + bhh[HH + h];
    float gc = g[2 * HH + h]   + bih[2 * HH + h]   + bhh[2 * HH + h];
    float go = g[3 * HH + h]   + bih[3 * HH + h]   + bhh[3 * HH + h];

    float si = 1.0f / (1.0f + expf(-gi));
    float sf = 1.0f / (1.0f + expf(-gf));
    float so = 1.0f / (1.0f + expf(-go));
    float c2 = sf * cp[b * HH + h] + si * tanhf(gc);
    float h2 = so * tanhf(c2);

    if (LAYER == 0) {
        g_H0[b * HH + h] = h2;
        g_C0[b * HH + h] = c2;
        g_XH1[b * KTOT + h] = h2;   // feed layer 1 GEMM input
    } else {
        g_H1[b * HH + h] = h2;
        g_C1[b * HH + h] = c2;
    }
}

// ---------------- scatter new row + compute h_out/c_out ----------------
__global__ void k_scatter(const float* __restrict__ hs_in,
                          const float* __restrict__ cs_in,
                          const int* __restrict__ op,
                          const int* __restrict__ pos,
                          float* __restrict__ out) {
    float* __restrict__ h_out  = out;                 // (1,B,L)
    float* __restrict__ c_out  = out + BB * LL;       // (1,B,L)
    float* __restrict__ hs_out = out + 2 * BB * LL;
    float* __restrict__ cs_out = hs_out + STACKN;

    int b = blockIdx.x;
    int h = threadIdx.x;
    int p = pos[b];

    size_t base = (((size_t)(p + 1) * BB + b) * HH + h) * LL;
    float h0 = g_H0[b * HH + h], h1 = g_H1[b * HH + h];
    float c0 = g_C0[b * HH + h], c1 = g_C1[b * HH + h];
    *(float2*)(hs_out + base) = make_float2(h0, h1);
    *(float2*)(cs_out + base) = make_float2(c0, c1);

    if (h == 0) {
        int o  = op[b];
        int np = p + o;
        float2 hv, cv;
        if (o == 1) {
            hv = make_float2(g_H0[b * HH + (HH - 1)], g_H1[b * HH + (HH - 1)]);
            cv = make_float2(g_C0[b * HH + (HH - 1)], g_C1[b * HH + (HH - 1)]);
        } else {
            size_t gi = (((size_t)np * BB + b) * HH + (HH - 1)) * LL;
            hv = *(const float2*)(hs_in + gi);
            cv = *(const float2*)(cs_in + gi);
        }
        *(float2*)(h_out + b * LL) = hv;
        *(float2*)(c_out + b * LL) = cv;
    }
}

// ---------------- launch ----------------
extern "C" void kernel_launch(void* const* d_in, const int* in_sizes, int n_in,
                              void* d_out, int out_size) {
    const float* x    = (const float*)d_in[0];
    const float* hs   = (const float*)d_in[1];
    const float* cs   = (const float*)d_in[2];
    const float* wih0 = (const float*)d_in[3];
    const float* whh0 = (const float*)d_in[4];
    const float* bih0 = (const float*)d_in[5];
    const float* bhh0 = (const float*)d_in[6];
    const float* wih1 = (const float*)d_in[7];
    const float* whh1 = (const float*)d_in[8];
    const float* bih1 = (const float*)d_in[9];
    const float* bhh1 = (const float*)d_in[10];
    const int*   op   = (const int*)d_in[11];
    const int*   pos  = (const int*)d_in[12];
    float* out = (float*)d_out;

    float* hs_out = out + 2 * BB * LL;
    float* cs_out = hs_out + STACKN;

    k_gather<<<BB, HH>>>(x, hs, cs, pos);
    k_gemm_copy<0><<<GEMM_CTAS + COPY_CTAS, 256>>>(wih0, whh0, hs, hs_out);
    k_act<0><<<BB, HH>>>(bih0, bhh0);
    k_gemm_copy<1><<<GEMM_CTAS + COPY_CTAS, 256>>>(wih1, whh1, cs, cs_out);
    k_act<1><<<BB, HH>>>(bih1, bhh1);
    k_scatter<<<BB, HH>>>(hs, cs, op, pos, out);
}

// round 3
// speedup vs baseline: 1.0684x; 1.0638x over previous
#include <cuda_runtime.h>
#include <math.h>

#define BB 256
#define INF 256
#define HH 256
#define LL 2
#define SS 128
#define NSTK (SS + 1)
#define KTOT 512          // IN + H concatenated GEMM K
#define NG 1024           // 4*H gates

#define GEMM_CTAS 64      // (1024/64) * (256/64) tiles of 64x64
#define STACKN ((size_t)NSTK * BB * HH * LL)      // floats per stack
#define ROWS_PER_STACK ((long)NSTK * BB)          // 33024 rows of 512 floats
#define ROWS_TOTAL (2 * ROWS_PER_STACK)           // 66048

// copy chunk schedule (rows)
#define R_GATHER 10000L
#define R_GEMM0  17000L
#define R_ACT0   4000L
#define R_GEMM1  17000L
#define R_ACT1   6000L
// remainder in final kernel

// ---------------- scratch ----------------
__device__ float g_XH0[BB * KTOT];   // [x | h_prev0]
__device__ float g_XH1[BB * KTOT];   // [h0 | h_prev1]
__device__ float g_G0[BB * NG];
__device__ float g_G1[BB * NG];
__device__ float g_Cp0[BB * HH];
__device__ float g_Cp1[BB * HH];
__device__ float g_H0[BB * HH];
__device__ float g_C0[BB * HH];

// ---------------- warp-per-row copy helper ----------------
// row r in [0, ROWS_TOTAL): r < ROWS_PER_STACK -> hs, else cs.
// Each row = 512 floats (one (s,b) slice). Skip rows s == pos[b]+1 (scatter owns them).
__device__ __forceinline__ void copy_rows(const float* __restrict__ hs,
                                          const float* __restrict__ cs,
                                          float* __restrict__ hs_out,
                                          float* __restrict__ cs_out,
                                          const int* __restrict__ pos,
                                          long row_start, long row_end,
                                          int gwarp, int nwarps, int lane) {
    for (long r = row_start + gwarp; r < row_end; r += nwarps) {
        long rs = r;
        const float* src;
        float* dst;
        if (rs < ROWS_PER_STACK) { src = hs; dst = hs_out; }
        else { rs -= ROWS_PER_STACK; src = cs; dst = cs_out; }
        int s = (int)(rs >> 8);          // / BB
        int b = (int)(rs & 255);         // % BB
        if (s == pos[b] + 1) continue;   // scatter writes this row
        const float4* s4 = (const float4*)(src + rs * 512);
        float4* d4 = (float4*)(dst + rs * 512);
        float4 v0 = s4[lane];
        float4 v1 = s4[lane + 32];
        float4 v2 = s4[lane + 64];
        float4 v3 = s4[lane + 96];
        d4[lane]      = v0;
        d4[lane + 32] = v1;
        d4[lane + 64] = v2;
        d4[lane + 96] = v3;
    }
}

#define COPY_ROLE(ROLE_CTAS, COPY_CTAS)                                         \
    do {                                                                        \
        int gwarp = (blockIdx.x - (ROLE_CTAS)) * 8 + (threadIdx.x >> 5);        \
        copy_rows(hs, cs, hs_out, cs_out, pos, row_start, row_end,              \
                  gwarp, (COPY_CTAS) * 8, threadIdx.x & 31);                    \
    } while (0)

// ---------------- gather + copy ----------------
#define GATHER_COPY_CTAS 192
__global__ void __launch_bounds__(256) k_gather(const float* __restrict__ x,
                         const float* __restrict__ hs,
                         const float* __restrict__ cs,
                         const int* __restrict__ pos,
                         float* __restrict__ hs_out, float* __restrict__ cs_out,
                         long row_start, long row_end) {
    if (blockIdx.x >= BB) { COPY_ROLE(BB, GATHER_COPY_CTAS); return; }
    int b = blockIdx.x;
    int h = threadIdx.x;
    int s = pos[b];
    size_t idx = (((size_t)s * BB + b) * HH + h) * LL;
    float2 hv = *(const float2*)(hs + idx);
    float2 cv = *(const float2*)(cs + idx);
    g_XH0[b * KTOT + h]       = x[b * INF + h];
    g_XH0[b * KTOT + INF + h] = hv.x;
    g_XH1[b * KTOT + INF + h] = hv.y;
    g_Cp0[b * HH + h] = cv.x;
    g_Cp1[b * HH + h] = cv.y;
}

// ---------------- GEMM (64x64 tile, BK=16, prefetch) + copy ----------------
#define GEMM_COPY_CTAS 232
template <int LAYER>
__global__ void __launch_bounds__(256) k_gemm(const float* __restrict__ Wih,
                                              const float* __restrict__ Whh,
                                              const float* __restrict__ hs,
                                              const float* __restrict__ cs,
                                              float* __restrict__ hs_out,
                                              float* __restrict__ cs_out,
                                              const int* __restrict__ pos,
                                              long row_start, long row_end) {
    if (blockIdx.x >= GEMM_CTAS) { COPY_ROLE(GEMM_CTAS, GEMM_COPY_CTAS); return; }

    const float* __restrict__ A = LAYER ? g_XH1 : g_XH0;
    float* __restrict__ Cout    = LAYER ? g_G1 : g_G0;

    __shared__ float As[16][68];
    __shared__ float Bs[16][68];

    const int bid = blockIdx.x;
    const int t   = threadIdx.x;
    const int n0 = (bid & 15) * 64;
    const int m0 = (bid >> 4) * 64;
    const int tx = t & 15;
    const int ty = t >> 4;
    const int lrow = t >> 2;
    const int lc4  = (t & 3) * 4;

    float acc[4][4];
#pragma unroll
    for (int i = 0; i < 4; i++)
#pragma unroll
        for (int j = 0; j < 4; j++) acc[i][j] = 0.f;

    // prefetch first tiles
    float4 av = *(const float4*)(A + (size_t)(m0 + lrow) * KTOT + lc4);
    float4 bv = *(const float4*)(Wih + (size_t)(n0 + lrow) * INF + lc4);

    for (int k0 = 0; k0 < KTOT; k0 += 16) {
        As[lc4 + 0][lrow] = av.x;
        As[lc4 + 1][lrow] = av.y;
        As[lc4 + 2][lrow] = av.z;
        As[lc4 + 3][lrow] = av.w;
        Bs[lc4 + 0][lrow] = bv.x;
        Bs[lc4 + 1][lrow] = bv.y;
        Bs[lc4 + 2][lrow] = bv.z;
        Bs[lc4 + 3][lrow] = bv.w;
        __syncthreads();

        int k1 = k0 + 16;
        if (k1 < KTOT) {
            av = *(const float4*)(A + (size_t)(m0 + lrow) * KTOT + k1 + lc4);
            const float* __restrict__ Wp = (k1 < INF) ? Wih : Whh;
            int kcol = (k1 < INF) ? k1 : (k1 - INF);
            bv = *(const float4*)(Wp + (size_t)(n0 + lrow) * INF + kcol + lc4);
        }

#pragma unroll
        for (int kk = 0; kk < 16; kk++) {
            float4 a4 = *(const float4*)(&As[kk][ty * 4]);
            float4 b4 = *(const float4*)(&Bs[kk][tx * 4]);
            acc[0][0] += a4.x * b4.x; acc[0][1] += a4.x * b4.y;
            acc[0][2] += a4.x * b4.z; acc[0][3] += a4.x * b4.w;
            acc[1][0] += a4.y * b4.x; acc[1][1] += a4.y * b4.y;
            acc[1][2] += a4.y * b4.z; acc[1][3] += a4.y * b4.w;
            acc[2][0] += a4.z * b4.x; acc[2][1] += a4.z * b4.y;
            acc[2][2] += a4.z * b4.z; acc[2][3] += a4.z * b4.w;
            acc[3][0] += a4.w * b4.x; acc[3][1] += a4.w * b4.y;
            acc[3][2] += a4.w * b4.z; acc[3][3] += a4.w * b4.w;
        }
        __syncthreads();
    }

#pragma unroll
    for (int i = 0; i < 4; i++) {
        int m = m0 + ty * 4 + i;
        int n = n0 + tx * 4;
        *(float4*)(Cout + (size_t)m * NG + n) =
            make_float4(acc[i][0], acc[i][1], acc[i][2], acc[i][3]);
    }
}

// ---------------- act0 + copy ----------------
#define ACT_COPY_CTAS 192
__global__ void __launch_bounds__(256) k_act0(const float* __restrict__ bih, const float* __restrict__ bhh,
                       const float* __restrict__ hs, const float* __restrict__ cs,
                       float* __restrict__ hs_out, float* __restrict__ cs_out,
                       const int* __restrict__ pos,
                       long row_start, long row_end) {
    if (blockIdx.x >= BB) { COPY_ROLE(BB, ACT_COPY_CTAS); return; }
    int b = blockIdx.x;
    int h = threadIdx.x;
    const float* __restrict__ g = g_G0 + (size_t)b * NG;

    float gi = g[h]          + bih[h]          + bhh[h];
    float gf = g[HH + h]     + bih[HH + h]     + bhh[HH + h];
    float gc = g[2 * HH + h] + bih[2 * HH + h] + bhh[2 * HH + h];
    float go = g[3 * HH + h] + bih[3 * HH + h] + bhh[3 * HH + h];

    float si = 1.0f / (1.0f + expf(-gi));
    float sf = 1.0f / (1.0f + expf(-gf));
    float so = 1.0f / (1.0f + expf(-go));
    float c2 = sf * g_Cp0[b * HH + h] + si * tanhf(gc);
    float h2 = so * tanhf(c2);

    g_H0[b * HH + h] = h2;
    g_C0[b * HH + h] = c2;
    g_XH1[b * KTOT + h] = h2;
}

// ---------------- act1 + scatter + outputs + copy ----------------
__global__ void __launch_bounds__(256) k_act1(const float* __restrict__ bih, const float* __restrict__ bhh,
                       const float* __restrict__ hs, const float* __restrict__ cs,
                       float* __restrict__ hs_out, float* __restrict__ cs_out,
                       const int* __restrict__ op, const int* __restrict__ pos,
                       float* __restrict__ out,
                       long row_start, long row_end) {
    if (blockIdx.x >= BB) { COPY_ROLE(BB, ACT_COPY_CTAS); return; }
    int b = blockIdx.x;
    int h = threadIdx.x;
    const float* __restrict__ g = g_G1 + (size_t)b * NG;

    float gi = g[h]          + bih[h]          + bhh[h];
    float gf = g[HH + h]     + bih[HH + h]     + bhh[HH + h];
    float gc = g[2 * HH + h] + bih[2 * HH + h] + bhh[2 * HH + h];
    float go = g[3 * HH + h] + bih[3 * HH + h] + bhh[3 * HH + h];

    float si = 1.0f / (1.0f + expf(-gi));
    float sf = 1.0f / (1.0f + expf(-gf));
    float so = 1.0f / (1.0f + expf(-go));
    float c2 = sf * g_Cp1[b * HH + h] + si * tanhf(gc);
    float h2 = so * tanhf(c2);

    int p = pos[b];
    float h0 = g_H0[b * HH + h];
    float c0 = g_C0[b * HH + h];
    size_t base = (((size_t)(p + 1) * BB + b) * HH + h) * LL;
    *(float2*)(hs_out + base) = make_float2(h0, h2);
    *(float2*)(cs_out + base) = make_float2(c0, c2);

    if (h == HH - 1) {
        float* __restrict__ h_out = out;
        float* __restrict__ c_out = out + BB * LL;
        int o = op[b];
        float2 hv, cv;
        if (o == 1) {
            hv = make_float2(h0, h2);
            cv = make_float2(c0, c2);
        } else {
            size_t gi2 = (((size_t)(p + o) * BB + b) * HH + (HH - 1)) * LL;
            hv = *(const float2*)(hs + gi2);
            cv = *(const float2*)(cs + gi2);
        }
        *(float2*)(h_out + b * LL) = hv;
        *(float2*)(c_out + b * LL) = cv;
    }
}

// ---------------- final copy remainder ----------------
#define FINAL_COPY_CTAS 296
__global__ void __launch_bounds__(256) k_copy(const float* __restrict__ hs, const float* __restrict__ cs,
                       float* __restrict__ hs_out, float* __restrict__ cs_out,
                       const int* __restrict__ pos,
                       long row_start, long row_end) {
    int gwarp = blockIdx.x * 8 + (threadIdx.x >> 5);
    copy_rows(hs, cs, hs_out, cs_out, pos, row_start, row_end,
              gwarp, FINAL_COPY_CTAS * 8, threadIdx.x & 31);
}

// ---------------- launch ----------------
extern "C" void kernel_launch(void* const* d_in, const int* in_sizes, int n_in,
                              void* d_out, int out_size) {
    const float* x    = (const float*)d_in[0];
    const float* hs   = (const float*)d_in[1];
    const float* cs   = (const float*)d_in[2];
    const float* wih0 = (const float*)d_in[3];
    const float* whh0 = (const float*)d_in[4];
    const float* bih0 = (const float*)d_in[5];
    const float* bhh0 = (const float*)d_in[6];
    const float* wih1 = (const float*)d_in[7];
    const float* whh1 = (const float*)d_in[8];
    const float* bih1 = (const float*)d_in[9];
    const float* bhh1 = (const float*)d_in[10];
    const int*   op   = (const int*)d_in[11];
    const int*   pos  = (const int*)d_in[12];
    float* out = (float*)d_out;

    float* hs_out = out + 2 * BB * LL;
    float* cs_out = hs_out + STACKN;

    long r0 = 0;
    long r1 = r0 + R_GATHER;
    long r2 = r1 + R_GEMM0;
    long r3 = r2 + R_ACT0;
    long r4 = r3 + R_GEMM1;
    long r5 = r4 + R_ACT1;

    k_gather<<<BB + GATHER_COPY_CTAS, 256>>>(x, hs, cs, pos, hs_out, cs_out, r0, r1);
    k_gemm<0><<<GEMM_CTAS + GEMM_COPY_CTAS, 256>>>(wih0, whh0, hs, cs, hs_out, cs_out, pos, r1, r2);
    k_act0<<<BB + ACT_COPY_CTAS, 256>>>(bih0, bhh0, hs, cs, hs_out, cs_out, pos, r2, r3);
    k_gemm<1><<<GEMM_CTAS + GEMM_COPY_CTAS, 256>>>(wih1, whh1, hs, cs, hs_out, cs_out, pos, r3, r4);
    k_act1<<<BB + ACT_COPY_CTAS, 256>>>(bih1, bhh1, hs, cs, hs_out, cs_out, op, pos, out, r4, r5);
    k_copy<<<FINAL_COPY_CTAS, 256>>>(hs, cs, hs_out, cs_out, pos, r5, ROWS_TOTAL);
}

// round 6
// speedup vs baseline: 1.1978x; 1.1210x over previous
#include <cuda_runtime.h>
#include <cuda_bf16.h>
#include <math.h>
#include <stdint.h>

#define BB 256
#define INF 256
#define HH 256
#define KTOT 512
#define NG 1024
#define NSTK 129
#define STACKN ((size_t)NSTK * BB * HH * 2)
#define ROWS_PER_STACK ((long)NSTK * BB)       // 33024
#define ROWS_TOTAL (2 * ROWS_PER_STACK)        // 66048

// copy schedule (rows of 512 floats = 2KB)
#define R_PRO 8000L
#define R_G0  6000L
#define R_A0  3000L
#define R_G1  6000L
#define R_A1  3000L

// ---------------- scratch ----------------
__device__ float g_G0[BB * NG];
__device__ float g_G1[BB * NG];
__device__ float g_Cp0[BB * HH], g_Cp1[BB * HH];
__device__ float g_H0[BB * HH], g_C0[BB * HH];
__device__ __align__(16) __nv_bfloat16 g_XH0hi[BB * KTOT], g_XH0lo[BB * KTOT];
__device__ __align__(16) __nv_bfloat16 g_XH1hi[BB * KTOT], g_XH1lo[BB * KTOT];
__device__ __align__(16) __nv_bfloat16 g_W0hi[NG * KTOT], g_W0lo[NG * KTOT];
__device__ __align__(16) __nv_bfloat16 g_W1hi[NG * KTOT], g_W1lo[NG * KTOT];

__device__ __forceinline__ uint32_t smem_u32(const void* p) {
    uint32_t a;
    asm("{ .reg .u64 t; cvta.to.shared.u64 t, %1; cvt.u32.u64 %0, t; }" : "=r"(a) : "l"(p));
    return a;
}
__device__ __forceinline__ void cp16(uint32_t saddr, const void* gaddr) {
    asm volatile("cp.async.cg.shared.global [%0], [%1], 16;" :: "r"(saddr), "l"(gaddr));
}
#define CP_COMMIT() asm volatile("cp.async.commit_group;" ::: "memory")
#define CP_WAIT(n)  asm volatile("cp.async.wait_group %0;" :: "n"(n) : "memory")

__device__ __forceinline__ void bfsplit(float v, __nv_bfloat16& hi, __nv_bfloat16& lo) {
    hi = __float2bfloat16(v);
    lo = __float2bfloat16(v - __bfloat162float(hi));
}

__device__ __forceinline__ void hmma(float* c, uint32_t a0, uint32_t a1, uint32_t a2, uint32_t a3,
                                     uint32_t b0, uint32_t b1) {
    asm volatile(
        "mma.sync.aligned.m16n8k16.row.col.f32.bf16.bf16.f32 "
        "{%0,%1,%2,%3}, {%4,%5,%6,%7}, {%8,%9}, {%0,%1,%2,%3};"
        : "+f"(c[0]), "+f"(c[1]), "+f"(c[2]), "+f"(c[3])
        : "r"(a0), "r"(a1), "r"(a2), "r"(a3), "r"(b0), "r"(b1));
}

// ---------------- warp-per-row copy helper ----------------
__device__ __forceinline__ void copy_rows(const float* __restrict__ hs,
                                          const float* __restrict__ cs,
                                          float* __restrict__ hs_out,
                                          float* __restrict__ cs_out,
                                          const int* __restrict__ pos,
                                          long row_start, long row_end,
                                          int gwarp, int nwarps, int lane) {
    for (long r = row_start + gwarp; r < row_end; r += nwarps) {
        long rs = r;
        const float* src;
        float* dst;
        if (rs < ROWS_PER_STACK) { src = hs; dst = hs_out; }
        else { rs -= ROWS_PER_STACK; src = cs; dst = cs_out; }
        int s = (int)(rs >> 8);
        int b = (int)(rs & 255);
        if (s == pos[b] + 1) continue;
        const float4* s4 = (const float4*)(src + rs * 512);
        float4* d4 = (float4*)(dst + rs * 512);
        float4 v0 = s4[lane];
        float4 v1 = s4[lane + 32];
        float4 v2 = s4[lane + 64];
        float4 v3 = s4[lane + 96];
        d4[lane] = v0; d4[lane + 32] = v1; d4[lane + 64] = v2; d4[lane + 96] = v3;
    }
}
#define COPY_ROLE(ROLE_CTAS, COPY_CTAS)                                   \
    do {                                                                  \
        int gwarp = (blockIdx.x - (ROLE_CTAS)) * 8 + (threadIdx.x >> 5);  \
        copy_rows(hs, cs, hs_out, cs_out, pos, row_start, row_end,        \
                  gwarp, (COPY_CTAS) * 8, threadIdx.x & 31);              \
    } while (0)

// ---------------- prologue: gather + weight split + copy ----------------
#define WPREP_CTAS 128
#define PRO_COPY_CTAS 256
union BF8U { __nv_bfloat16 b[8]; uint4 u; };

__global__ void __launch_bounds__(256) k_prologue(
        const float* __restrict__ x, const float* __restrict__ hs, const float* __restrict__ cs,
        const float* __restrict__ wih0, const float* __restrict__ whh0,
        const float* __restrict__ wih1, const float* __restrict__ whh1,
        const int* __restrict__ pos,
        float* __restrict__ hs_out, float* __restrict__ cs_out,
        long row_start, long row_end) {
    int bid = blockIdx.x;
    int t = threadIdx.x;
    if (bid < BB) {
        int b = bid, h = t;
        int s = pos[b];
        size_t idx = (((size_t)s * BB + b) * HH + h) * 2;
        float2 hv = *(const float2*)(hs + idx);
        float2 cv = *(const float2*)(cs + idx);
        __nv_bfloat16 hi, lo;
        bfsplit(x[b * INF + h], hi, lo);
        g_XH0hi[b * KTOT + h] = hi; g_XH0lo[b * KTOT + h] = lo;
        bfsplit(hv.x, hi, lo);
        g_XH0hi[b * KTOT + INF + h] = hi; g_XH0lo[b * KTOT + INF + h] = lo;
        bfsplit(hv.y, hi, lo);
        g_XH1hi[b * KTOT + INF + h] = hi; g_XH1lo[b * KTOT + INF + h] = lo;
        g_Cp0[b * HH + h] = cv.x;
        g_Cp1[b * HH + h] = cv.y;
        return;
    }
    if (bid < BB + WPREP_CTAS) {
        int tid0 = (bid - BB) * 256 + t;
        for (int g = tid0; g < 2 * NG * 64; g += WPREP_CTAS * 256) {
            int layer = g >> 16;
            int rem = g & 65535;
            int n = rem >> 6;
            int k8 = (rem & 63) * 8;
            const float* wih = layer ? wih1 : wih0;
            const float* whh = layer ? whh1 : whh0;
            const float* srcp = (k8 < INF) ? (wih + (size_t)n * INF + k8)
                                           : (whh + (size_t)n * INF + (k8 - INF));
            float4 a = *(const float4*)srcp;
            float4 bq = *(const float4*)(srcp + 4);
            float v[8] = {a.x, a.y, a.z, a.w, bq.x, bq.y, bq.z, bq.w};
            BF8U uhi, ulo;
#pragma unroll
            for (int j = 0; j < 8; j++) bfsplit(v[j], uhi.b[j], ulo.b[j]);
            __nv_bfloat16* dhi = layer ? g_W1hi : g_W0hi;
            __nv_bfloat16* dlo = layer ? g_W1lo : g_W0lo;
            *(uint4*)(dhi + (size_t)n * KTOT + k8) = uhi.u;
            *(uint4*)(dlo + (size_t)n * KTOT + k8) = ulo.u;
        }
        return;
    }
    COPY_ROLE(BB + WPREP_CTAS, PRO_COPY_CTAS);
}

// ---------------- HMMA GEMM: G[256,1024] = XH[256,512] @ W[1024,512]^T ----------------
// CTA tile 64x128, 8 warps (2x4), warp tile 32x32. K chunks of 32, cp.async double buffer.
// 3-term bf16 split: AhiBhi + AhiBlo + AloBhi.
#define GEMM_CTAS 32
#define GEMM_COPY_CTAS 232
#define APAD 40                       // bf16 row stride in smem (conflict-free)
#define A_BYTES (64 * APAD * 2)       // 5120 per hi/lo array
#define B_BYTES (128 * APAD * 2)      // 10240 per hi/lo array
#define STAGE_BYTES (2 * A_BYTES + 2 * B_BYTES)   // 30720
#define SMEM_GEMM (2 * STAGE_BYTES)               // 61440
#define OFF_AH(p) ((p) * STAGE_BYTES)
#define OFF_AL(p) ((p) * STAGE_BYTES + A_BYTES)
#define OFF_BH(p) ((p) * STAGE_BYTES + 2 * A_BYTES)
#define OFF_BL(p) ((p) * STAGE_BYTES + 2 * A_BYTES + B_BYTES)

template <int LAYER>
__global__ void __launch_bounds__(256) k_gemm(
        const float* __restrict__ hs, const float* __restrict__ cs,
        float* __restrict__ hs_out, float* __restrict__ cs_out,
        const int* __restrict__ pos, long row_start, long row_end) {
    const int bid = blockIdx.x;
    const int t = threadIdx.x;
    if (bid >= GEMM_CTAS) { COPY_ROLE(GEMM_CTAS, GEMM_COPY_CTAS); return; }

    extern __shared__ char smem[];
    const uint32_t sb = smem_u32(smem);

    const __nv_bfloat16* __restrict__ Ahi = LAYER ? g_XH1hi : g_XH0hi;
    const __nv_bfloat16* __restrict__ Alo = LAYER ? g_XH1lo : g_XH0lo;
    const __nv_bfloat16* __restrict__ Bhi = LAYER ? g_W1hi : g_W0hi;
    const __nv_bfloat16* __restrict__ Blo = LAYER ? g_W1lo : g_W0lo;
    float* __restrict__ Cout = LAYER ? g_G1 : g_G0;

    const int m0 = (bid & 3) * 64;     // 4 m tiles
    const int n0 = (bid >> 2) * 128;   // 8 n tiles
    const int wid = t >> 5, lane = t & 31;
    const int wm = (wid >> 2) * 32;    // warp m offset (0/32)
    const int wn = (wid & 3) * 32;     // warp n offset (0..96)

    // per-thread cp.async assignments: A: 2 uint4 (hi+lo), B: 4 uint4
    const int arow = t >> 2, aj = t & 3;              // A: 64 rows x 4
    const int brow0 = t >> 1, bj0 = (t & 1) * 2;      // B: 128 rows x 4 -> 2 per thread x2 arrays

    float acc[2][4][4];
#pragma unroll
    for (int i = 0; i < 2; i++)
#pragma unroll
        for (int j = 0; j < 4; j++)
#pragma unroll
            for (int q = 0; q < 4; q++) acc[i][j][q] = 0.f;

    // load chunk c into stage p
    auto load_chunk = [&](int c, int p) {
        int kc = c * 32;
        // A hi/lo: row arow, 8 bf16 at aj*8
        const __nv_bfloat16* ga = Ahi + (size_t)(m0 + arow) * KTOT + kc + aj * 8;
        cp16(sb + OFF_AH(p) + arow * (APAD * 2) + aj * 16, ga);
        ga = Alo + (size_t)(m0 + arow) * KTOT + kc + aj * 8;
        cp16(sb + OFF_AL(p) + arow * (APAD * 2) + aj * 16, ga);
        // B hi/lo: rows brow0, cols bj0 and bj0+1
#pragma unroll
        for (int e = 0; e < 2; e++) {
            const __nv_bfloat16* gb = Bhi + (size_t)(n0 + brow0) * KTOT + kc + (bj0 + e) * 8;
            cp16(sb + OFF_BH(p) + brow0 * (APAD * 2) + (bj0 + e) * 16, gb);
            gb = Blo + (size_t)(n0 + brow0) * KTOT + kc + (bj0 + e) * 8;
            cp16(sb + OFF_BL(p) + brow0 * (APAD * 2) + (bj0 + e) * 16, gb);
        }
    };

    load_chunk(0, 0);
    CP_COMMIT();

    const int lr = lane >> 2;          // 0..7
    const int lc = (lane & 3) * 2;     // 0,2,4,6

#pragma unroll 1
    for (int c = 0; c < 16; c++) {
        int p = c & 1;
        if (c + 1 < 16) {
            load_chunk(c + 1, p ^ 1);
            CP_COMMIT();
            CP_WAIT(1);
        } else {
            CP_WAIT(0);
        }
        __syncthreads();

        const __nv_bfloat16* ah = (const __nv_bfloat16*)(smem + OFF_AH(p));
        const __nv_bfloat16* al = (const __nv_bfloat16*)(smem + OFF_AL(p));
        const __nv_bfloat16* bh = (const __nv_bfloat16*)(smem + OFF_BH(p));
        const __nv_bfloat16* bl = (const __nv_bfloat16*)(smem + OFF_BL(p));

#pragma unroll
        for (int k0 = 0; k0 < 32; k0 += 16) {
            uint32_t AH[2][4], AL[2][4], BH[4][2], BL[4][2];
#pragma unroll
            for (int mt = 0; mt < 2; mt++) {
                int r = wm + mt * 16 + lr;
                int cc = k0 + lc;
                AH[mt][0] = *(const uint32_t*)(ah + r * APAD + cc);
                AH[mt][1] = *(const uint32_t*)(ah + (r + 8) * APAD + cc);
                AH[mt][2] = *(const uint32_t*)(ah + r * APAD + cc + 8);
                AH[mt][3] = *(const uint32_t*)(ah + (r + 8) * APAD + cc + 8);
                AL[mt][0] = *(const uint32_t*)(al + r * APAD + cc);
                AL[mt][1] = *(const uint32_t*)(al + (r + 8) * APAD + cc);
                AL[mt][2] = *(const uint32_t*)(al + r * APAD + cc + 8);
                AL[mt][3] = *(const uint32_t*)(al + (r + 8) * APAD + cc + 8);
            }
#pragma unroll
            for (int nt = 0; nt < 4; nt++) {
                int n = wn + nt * 8 + lr;
                int cc = k0 + lc;
                BH[nt][0] = *(const uint32_t*)(bh + n * APAD + cc);
                BH[nt][1] = *(const uint32_t*)(bh + n * APAD + cc + 8);
                BL[nt][0] = *(const uint32_t*)(bl + n * APAD + cc);
                BL[nt][1] = *(const uint32_t*)(bl + n * APAD + cc + 8);
            }
#pragma unroll
            for (int mt = 0; mt < 2; mt++)
#pragma unroll
                for (int nt = 0; nt < 4; nt++) {
                    hmma(acc[mt][nt], AH[mt][0], AH[mt][1], AH[mt][2], AH[mt][3], BH[nt][0], BH[nt][1]);
                    hmma(acc[mt][nt], AH[mt][0], AH[mt][1], AH[mt][2], AH[mt][3], BL[nt][0], BL[nt][1]);
                    hmma(acc[mt][nt], AL[mt][0], AL[mt][1], AL[mt][2], AL[mt][3], BH[nt][0], BH[nt][1]);
                }
        }
        __syncthreads();
    }

    // epilogue
#pragma unroll
    for (int mt = 0; mt < 2; mt++) {
        int r = m0 + wm + mt * 16 + lr;
#pragma unroll
        for (int nt = 0; nt < 4; nt++) {
            int n = n0 + wn + nt * 8 + lc;
            *(float2*)(Cout + (size_t)r * NG + n)       = make_float2(acc[mt][nt][0], acc[mt][nt][1]);
            *(float2*)(Cout + (size_t)(r + 8) * NG + n) = make_float2(acc[mt][nt][2], acc[mt][nt][3]);
        }
    }
}

// ---------------- act0 + copy ----------------
#define ACT_COPY_CTAS 192
__global__ void __launch_bounds__(256) k_act0(
        const float* __restrict__ bih, const float* __restrict__ bhh,
        const float* __restrict__ hs, const float* __restrict__ cs,
        float* __restrict__ hs_out, float* __restrict__ cs_out,
        const int* __restrict__ pos, long row_start, long row_end) {
    if (blockIdx.x >= BB) { COPY_ROLE(BB, ACT_COPY_CTAS); return; }
    int b = blockIdx.x;
    int h = threadIdx.x;
    const float* __restrict__ g = g_G0 + (size_t)b * NG;

    float gi = g[h] + bih[h] + bhh[h];
    float gf = g[HH + h] + bih[HH + h] + bhh[HH + h];
    float gc = g[2 * HH + h] + bih[2 * HH + h] + bhh[2 * HH + h];
    float go = g[3 * HH + h] + bih[3 * HH + h] + bhh[3 * HH + h];

    float si = 1.0f / (1.0f + expf(-gi));
    float sf = 1.0f / (1.0f + expf(-gf));
    float so = 1.0f / (1.0f + expf(-go));
    float c2 = sf * g_Cp0[b * HH + h] + si * tanhf(gc);
    float h2 = so * tanhf(c2);

    g_H0[b * HH + h] = h2;
    g_C0[b * HH + h] = c2;
    __nv_bfloat16 hi, lo;
    bfsplit(h2, hi, lo);
    g_XH1hi[b * KTOT + h] = hi;
    g_XH1lo[b * KTOT + h] = lo;
}

// ---------------- act1 + scatter + outputs + copy ----------------
__global__ void __launch_bounds__(256) k_act1(
        const float* __restrict__ bih, const float* __restrict__ bhh,
        const float* __restrict__ hs, const float* __restrict__ cs,
        float* __restrict__ hs_out, float* __restrict__ cs_out,
        const int* __restrict__ op, const int* __restrict__ pos,
        float* __restrict__ out, long row_start, long row_end) {
    if (blockIdx.x >= BB) { COPY_ROLE(BB, ACT_COPY_CTAS); return; }
    int b = blockIdx.x;
    int h = threadIdx.x;
    const float* __restrict__ g = g_G1 + (size_t)b * NG;

    float gi = g[h] + bih[h] + bhh[h];
    float gf = g[HH + h] + bih[HH + h] + bhh[HH + h];
    float gc = g[2 * HH + h] + bih[2 * HH + h] + bhh[2 * HH + h];
    float go = g[3 * HH + h] + bih[3 * HH + h] + bhh[3 * HH + h];

    float si = 1.0f / (1.0f + expf(-gi));
    float sf = 1.0f / (1.0f + expf(-gf));
    float so = 1.0f / (1.0f + expf(-go));
    float c2 = sf * g_Cp1[b * HH + h] + si * tanhf(gc);
    float h2 = so * tanhf(c2);

    int p = pos[b];
    float h0 = g_H0[b * HH + h];
    float c0 = g_C0[b * HH + h];
    size_t base = (((size_t)(p + 1) * BB + b) * HH + h) * 2;
    *(float2*)(hs_out + base) = make_float2(h0, h2);
    *(float2*)(cs_out + base) = make_float2(c0, c2);

    if (h == HH - 1) {
        float* __restrict__ h_out = out;
        float* __restrict__ c_out = out + BB * 2;
        int o = op[b];
        float2 hv, cv;
        if (o == 1) { hv = make_float2(h0, h2); cv = make_float2(c0, c2); }
        else {
            size_t gi2 = (((size_t)(p + o) * BB + b) * HH + (HH - 1)) * 2;
            hv = *(const float2*)(hs + gi2);
            cv = *(const float2*)(cs + gi2);
        }
        *(float2*)(h_out + b * 2) = hv;
        *(float2*)(c_out + b * 2) = cv;
    }
}

// ---------------- final copy ----------------
#define FINAL_COPY_CTAS 592
__global__ void __launch_bounds__(256) k_copy(
        const float* __restrict__ hs, const float* __restrict__ cs,
        float* __restrict__ hs_out, float* __restrict__ cs_out,
        const int* __restrict__ pos, long row_start, long row_end) {
    int gwarp = blockIdx.x * 8 + (threadIdx.x >> 5);
    copy_rows(hs, cs, hs_out, cs_out, pos, row_start, row_end,
              gwarp, FINAL_COPY_CTAS * 8, threadIdx.x & 31);
}

// ---------------- launch ----------------
extern "C" void kernel_launch(void* const* d_in, const int* in_sizes, int n_in,
                              void* d_out, int out_size) {
    const float* x    = (const float*)d_in[0];
    const float* hs   = (const float*)d_in[1];
    const float* cs   = (const float*)d_in[2];
    const float* wih0 = (const float*)d_in[3];
    const float* whh0 = (const float*)d_in[4];
    const float* bih0 = (const float*)d_in[5];
    const float* bhh0 = (const float*)d_in[6];
    const float* wih1 = (const float*)d_in[7];
    const float* whh1 = (const float*)d_in[8];
    const float* bih1 = (const float*)d_in[9];
    const float* bhh1 = (const float*)d_in[10];
    const int*   op   = (const int*)d_in[11];
    const int*   pos  = (const int*)d_in[12];
    float* out = (float*)d_out;

    float* hs_out = out + 2 * BB * 2;
    float* cs_out = hs_out + STACKN;

    static int smem_set = 0;
    if (!smem_set) {
        cudaFuncSetAttribute(k_gemm<0>, cudaFuncAttributeMaxDynamicSharedMemorySize, SMEM_GEMM);
        cudaFuncSetAttribute(k_gemm<1>, cudaFuncAttributeMaxDynamicSharedMemorySize, SMEM_GEMM);
        smem_set = 1;
    }

    long r0 = 0;
    long r1 = r0 + R_PRO;
    long r2 = r1 + R_G0;
    long r3 = r2 + R_A0;
    long r4 = r3 + R_G1;
    long r5 = r4 + R_A1;

    k_prologue<<<BB + WPREP_CTAS + PRO_COPY_CTAS, 256>>>(x, hs, cs, wih0, whh0, wih1, whh1,
                                                         pos, hs_out, cs_out, r0, r1);
    k_gemm<0><<<GEMM_CTAS + GEMM_COPY_CTAS, 256, SMEM_GEMM>>>(hs, cs, hs_out, cs_out, pos, r1, r2);
    k_act0<<<BB + ACT_COPY_CTAS, 256>>>(bih0, bhh0, hs, cs, hs_out, cs_out, pos, r2, r3);
    k_gemm<1><<<GEMM_CTAS + GEMM_COPY_CTAS, 256, SMEM_GEMM>>>(hs, cs, hs_out, cs_out, pos, r3, r4);
    k_act1<<<BB + ACT_COPY_CTAS, 256>>>(bih1, bhh1, hs, cs, hs_out, cs_out, op, pos, out, r4, r5);
    k_copy<<<FINAL_COPY_CTAS, 256>>>(hs, cs, hs_out, cs_out, pos, r5, ROWS_TOTAL);
}

// round 7
// speedup vs baseline: 1.4351x; 1.1981x over previous
#include <cuda_runtime.h>
#include <cuda_bf16.h>
#include <math.h>
#include <stdint.h>

#define BB 256
#define INF 256
#define HH 256
#define KTOT 512
#define NG 1024
#define NSTK 129
#define STACKN ((size_t)NSTK * BB * HH * 2)
#define ROWS_PER_STACK ((long)NSTK * BB)       // 33024
#define ROWS_TOTAL (2 * ROWS_PER_STACK)        // 66048

// copy schedule (rows of 512 floats = 2KB)
#define R_PRO 10000L
#define R_G0  9000L
#define R_G1  9000L

// ---------------- scratch ----------------
__device__ float g_Cp0[BB * HH], g_Cp1[BB * HH];
__device__ float g_H0[BB * HH], g_C0[BB * HH];
__device__ float g_Bias0[NG], g_Bias1[NG];     // gate-interleaved combined bias
__device__ __align__(16) __nv_bfloat16 g_XH0hi[BB * KTOT], g_XH0lo[BB * KTOT];
__device__ __align__(16) __nv_bfloat16 g_XH1hi[BB * KTOT], g_XH1lo[BB * KTOT];
__device__ __align__(16) __nv_bfloat16 g_W0hi[NG * KTOT], g_W0lo[NG * KTOT];   // [n'][k], n' = h*4+gate
__device__ __align__(16) __nv_bfloat16 g_W1hi[NG * KTOT], g_W1lo[NG * KTOT];

__device__ __forceinline__ uint32_t smem_u32(const void* p) {
    uint32_t a;
    asm("{ .reg .u64 t; cvta.to.shared.u64 t, %1; cvt.u32.u64 %0, t; }" : "=r"(a) : "l"(p));
    return a;
}
__device__ __forceinline__ void cp16(uint32_t saddr, const void* gaddr) {
    asm volatile("cp.async.cg.shared.global [%0], [%1], 16;" :: "r"(saddr), "l"(gaddr));
}
#define CP_COMMIT() asm volatile("cp.async.commit_group;" ::: "memory")
#define CP_WAIT(n)  asm volatile("cp.async.wait_group %0;" :: "n"(n) : "memory")

__device__ __forceinline__ void bfsplit(float v, __nv_bfloat16& hi, __nv_bfloat16& lo) {
    hi = __float2bfloat16(v);
    lo = __float2bfloat16(v - __bfloat162float(hi));
}

__device__ __forceinline__ void hmma(float* c, uint32_t a0, uint32_t a1, uint32_t a2, uint32_t a3,
                                     uint32_t b0, uint32_t b1) {
    asm volatile(
        "mma.sync.aligned.m16n8k16.row.col.f32.bf16.bf16.f32 "
        "{%0,%1,%2,%3}, {%4,%5,%6,%7}, {%8,%9}, {%0,%1,%2,%3};"
        : "+f"(c[0]), "+f"(c[1]), "+f"(c[2]), "+f"(c[3])
        : "r"(a0), "r"(a1), "r"(a2), "r"(a3), "r"(b0), "r"(b1));
}

// ---------------- warp-per-row copy helper ----------------
__device__ __forceinline__ void copy_rows(const float* __restrict__ hs,
                                          const float* __restrict__ cs,
                                          float* __restrict__ hs_out,
                                          float* __restrict__ cs_out,
                                          const int* __restrict__ pos,
                                          long row_start, long row_end,
                                          int gwarp, int nwarps, int lane) {
    for (long r = row_start + gwarp; r < row_end; r += nwarps) {
        long rs = r;
        const float* src;
        float* dst;
        if (rs < ROWS_PER_STACK) { src = hs; dst = hs_out; }
        else { rs -= ROWS_PER_STACK; src = cs; dst = cs_out; }
        int s = (int)(rs >> 8);
        int b = (int)(rs & 255);
        if (s == pos[b] + 1) continue;  // scatter (gemm1 epilogue) owns this row
        const float4* s4 = (const float4*)(src + rs * 512);
        float4* d4 = (float4*)(dst + rs * 512);
        float4 v0 = s4[lane];
        float4 v1 = s4[lane + 32];
        float4 v2 = s4[lane + 64];
        float4 v3 = s4[lane + 96];
        d4[lane] = v0; d4[lane + 32] = v1; d4[lane + 64] = v2; d4[lane + 96] = v3;
    }
}
#define COPY_ROLE(ROLE_CTAS, COPY_CTAS)                                   \
    do {                                                                  \
        int gwarp = (blockIdx.x - (ROLE_CTAS)) * 8 + (threadIdx.x >> 5);  \
        copy_rows(hs, cs, hs_out, cs_out, pos, row_start, row_end,        \
                  gwarp, (COPY_CTAS) * 8, threadIdx.x & 31);              \
    } while (0)

// ---------------- prologue: gather + weight split (gate-interleaved) + bias + copy ----------------
#define WPREP_CTAS 128
#define PRO_COPY_CTAS 256
union BF8U { __nv_bfloat16 b[8]; uint4 u; };

__global__ void __launch_bounds__(256) k_prologue(
        const float* __restrict__ x, const float* __restrict__ hs, const float* __restrict__ cs,
        const float* __restrict__ wih0, const float* __restrict__ whh0,
        const float* __restrict__ bih0, const float* __restrict__ bhh0,
        const float* __restrict__ wih1, const float* __restrict__ whh1,
        const float* __restrict__ bih1, const float* __restrict__ bhh1,
        const int* __restrict__ pos,
        float* __restrict__ hs_out, float* __restrict__ cs_out,
        long row_start, long row_end) {
    int bid = blockIdx.x;
    int t = threadIdx.x;
    if (bid < BB) {
        int b = bid, h = t;
        int s = pos[b];
        size_t idx = (((size_t)s * BB + b) * HH + h) * 2;
        float2 hv = *(const float2*)(hs + idx);
        float2 cv = *(const float2*)(cs + idx);
        __nv_bfloat16 hi, lo;
        bfsplit(x[b * INF + h], hi, lo);
        g_XH0hi[b * KTOT + h] = hi; g_XH0lo[b * KTOT + h] = lo;
        bfsplit(hv.x, hi, lo);
        g_XH0hi[b * KTOT + INF + h] = hi; g_XH0lo[b * KTOT + INF + h] = lo;
        bfsplit(hv.y, hi, lo);
        g_XH1hi[b * KTOT + INF + h] = hi; g_XH1lo[b * KTOT + INF + h] = lo;
        g_Cp0[b * HH + h] = cv.x;
        g_Cp1[b * HH + h] = cv.y;
        return;
    }
    if (bid < BB + WPREP_CTAS) {
        // weight split into bf16 hi/lo; layout [n'][k], n' = h*4+gate, k = [wih | whh]
        int tid0 = (bid - BB) * 256 + t;
        for (int g = tid0; g < 2 * NG * 64; g += WPREP_CTAS * 256) {
            int layer = g >> 16;
            int rem = g & 65535;
            int np = rem >> 6;               // n' 0..1023
            int k8 = (rem & 63) * 8;
            int hid = np >> 2, gate = np & 3;
            int orign = gate * HH + hid;
            const float* wih = layer ? wih1 : wih0;
            const float* whh = layer ? whh1 : whh0;
            const float* srcp = (k8 < INF) ? (wih + (size_t)orign * INF + k8)
                                           : (whh + (size_t)orign * INF + (k8 - INF));
            float4 a = *(const float4*)srcp;
            float4 bq = *(const float4*)(srcp + 4);
            float v[8] = {a.x, a.y, a.z, a.w, bq.x, bq.y, bq.z, bq.w};
            BF8U uhi, ulo;
#pragma unroll
            for (int j = 0; j < 8; j++) bfsplit(v[j], uhi.b[j], ulo.b[j]);
            __nv_bfloat16* dhi = layer ? g_W1hi : g_W0hi;
            __nv_bfloat16* dlo = layer ? g_W1lo : g_W0lo;
            *(uint4*)(dhi + (size_t)np * KTOT + k8) = uhi.u;
            *(uint4*)(dlo + (size_t)np * KTOT + k8) = ulo.u;
        }
        return;
    }
    if (bid == BB + WPREP_CTAS) {
        // combined bias in n'-space
#pragma unroll
        for (int e = 0; e < 8; e++) {
            int idx = e * 256 + t;
            int layer = idx >> 10;
            int np = idx & 1023;
            int hid = np >> 2, gate = np & 3;
            int orign = gate * HH + hid;
            float v = (layer ? bih1 : bih0)[orign] + (layer ? bhh1 : bhh0)[orign];
            (layer ? g_Bias1 : g_Bias0)[np] = v;
        }
        return;
    }
    COPY_ROLE(BB + WPREP_CTAS + 1, PRO_COPY_CTAS);
}

// ---------------- fused HMMA GEMM + LSTM epilogue + copy ----------------
// gates'[256, 1024] = XH[256,512] @ W'[1024,512]^T  (n' gate-interleaved)
// 64 CTAs: tile 64(m) x 64(n'), 8 warps (2m x 4n), warp tile 32x16.
// K chunks of 32, 4-stage cp.async pipeline. 3-term bf16 split.
#define GEMM_CTAS 64
#define GEMM_COPY_CTAS 192
#define APAD 40                          // bf16 row stride in smem
#define ARR_BYTES (64 * APAD * 2)        // 5120 per array
#define STAGE_BYTES (4 * ARR_BYTES)      // 20480 (AH, AL, BH, BL)
#define SMEM_GEMM (4 * STAGE_BYTES)      // 81920
#define OFF_AH(p) ((p) * STAGE_BYTES)
#define OFF_AL(p) ((p) * STAGE_BYTES + ARR_BYTES)
#define OFF_BH(p) ((p) * STAGE_BYTES + 2 * ARR_BYTES)
#define OFF_BL(p) ((p) * STAGE_BYTES + 3 * ARR_BYTES)
#define NCHUNK 16

template <int LAYER>
__global__ void __launch_bounds__(256) k_gemm(
        const float* __restrict__ hs, const float* __restrict__ cs,
        float* __restrict__ hs_out, float* __restrict__ cs_out,
        const int* __restrict__ op, const int* __restrict__ pos,
        float* __restrict__ out, long row_start, long row_end) {
    const int bid = blockIdx.x;
    const int t = threadIdx.x;
    if (bid >= GEMM_CTAS) { COPY_ROLE(GEMM_CTAS, GEMM_COPY_CTAS); return; }

    extern __shared__ char smem[];
    const uint32_t sb = smem_u32(smem);

    const __nv_bfloat16* __restrict__ Ahi = LAYER ? g_XH1hi : g_XH0hi;
    const __nv_bfloat16* __restrict__ Alo = LAYER ? g_XH1lo : g_XH0lo;
    const __nv_bfloat16* __restrict__ Bhi = LAYER ? g_W1hi : g_W0hi;
    const __nv_bfloat16* __restrict__ Blo = LAYER ? g_W1lo : g_W0lo;

    const int m0 = (bid & 3) * 64;      // 4 m tiles
    const int n0 = (bid >> 2) * 64;     // 16 n' tiles
    const int wid = t >> 5, lane = t & 31;
    const int wm = (wid & 1) * 32;      // warp m offset
    const int wn = (wid >> 1) * 16;     // warp n offset
    const int lr = lane >> 2;           // 0..7
    const int lc = (lane & 3) * 2;      // 0,2,4,6

    // cp.async per-thread assignment: 64 rows x 4 uint4-chunks, 1 per thread per array
    const int arow = t >> 2, aj = t & 3;

    float acc[2][2][4];
#pragma unroll
    for (int i = 0; i < 2; i++)
#pragma unroll
        for (int j = 0; j < 2; j++)
#pragma unroll
            for (int q = 0; q < 4; q++) acc[i][j][q] = 0.f;

    auto load_chunk = [&](int c, int p) {
        int kc = c * 32;
        cp16(sb + OFF_AH(p) + arow * (APAD * 2) + aj * 16,
             Ahi + (size_t)(m0 + arow) * KTOT + kc + aj * 8);
        cp16(sb + OFF_AL(p) + arow * (APAD * 2) + aj * 16,
             Alo + (size_t)(m0 + arow) * KTOT + kc + aj * 8);
        cp16(sb + OFF_BH(p) + arow * (APAD * 2) + aj * 16,
             Bhi + (size_t)(n0 + arow) * KTOT + kc + aj * 8);
        cp16(sb + OFF_BL(p) + arow * (APAD * 2) + aj * 16,
             Blo + (size_t)(n0 + arow) * KTOT + kc + aj * 8);
    };

    load_chunk(0, 0); CP_COMMIT();
    load_chunk(1, 1); CP_COMMIT();
    load_chunk(2, 2); CP_COMMIT();

#pragma unroll 1
    for (int c = 0; c < NCHUNK; c++) {
        int p = c & 3;
        if (c < NCHUNK - 2)      { CP_WAIT(2); }
        else if (c == NCHUNK - 2){ CP_WAIT(1); }
        else                     { CP_WAIT(0); }
        __syncthreads();
        if (c + 3 < NCHUNK) { load_chunk(c + 3, (c + 3) & 3); CP_COMMIT(); }

        const __nv_bfloat16* ah = (const __nv_bfloat16*)(smem + OFF_AH(p));
        const __nv_bfloat16* al = (const __nv_bfloat16*)(smem + OFF_AL(p));
        const __nv_bfloat16* bh = (const __nv_bfloat16*)(smem + OFF_BH(p));
        const __nv_bfloat16* bl = (const __nv_bfloat16*)(smem + OFF_BL(p));

#pragma unroll
        for (int k0 = 0; k0 < 32; k0 += 16) {
            uint32_t AH[2][4], AL[2][4], BH[2][2], BL[2][2];
#pragma unroll
            for (int mt = 0; mt < 2; mt++) {
                int r = wm + mt * 16 + lr;
                int cc = k0 + lc;
                AH[mt][0] = *(const uint32_t*)(ah + r * APAD + cc);
                AH[mt][1] = *(const uint32_t*)(ah + (r + 8) * APAD + cc);
                AH[mt][2] = *(const uint32_t*)(ah + r * APAD + cc + 8);
                AH[mt][3] = *(const uint32_t*)(ah + (r + 8) * APAD + cc + 8);
                AL[mt][0] = *(const uint32_t*)(al + r * APAD + cc);
                AL[mt][1] = *(const uint32_t*)(al + (r + 8) * APAD + cc);
                AL[mt][2] = *(const uint32_t*)(al + r * APAD + cc + 8);
                AL[mt][3] = *(const uint32_t*)(al + (r + 8) * APAD + cc + 8);
            }
#pragma unroll
            for (int nt = 0; nt < 2; nt++) {
                int n = wn + nt * 8 + lr;
                int cc = k0 + lc;
                BH[nt][0] = *(const uint32_t*)(bh + n * APAD + cc);
                BH[nt][1] = *(const uint32_t*)(bh + n * APAD + cc + 8);
                BL[nt][0] = *(const uint32_t*)(bl + n * APAD + cc);
                BL[nt][1] = *(const uint32_t*)(bl + n * APAD + cc + 8);
            }
#pragma unroll
            for (int mt = 0; mt < 2; mt++)
#pragma unroll
                for (int nt = 0; nt < 2; nt++) {
                    hmma(acc[mt][nt], AH[mt][0], AH[mt][1], AH[mt][2], AH[mt][3], BH[nt][0], BH[nt][1]);
                    hmma(acc[mt][nt], AH[mt][0], AH[mt][1], AH[mt][2], AH[mt][3], BL[nt][0], BL[nt][1]);
                    hmma(acc[mt][nt], AL[mt][0], AL[mt][1], AL[mt][2], AL[mt][3], BH[nt][0], BH[nt][1]);
                }
        }
        __syncthreads();
    }

    // ---- fused LSTM epilogue ----
    float* Gs = (float*)smem;   // 64 x 68 fp32 gates (pre-bias), reuses stage smem
    __syncthreads();
#pragma unroll
    for (int mt = 0; mt < 2; mt++)
#pragma unroll
        for (int nt = 0; nt < 2; nt++) {
            int r = wm + mt * 16 + lr;
            int n = wn + nt * 8 + lc;
            *(float2*)(Gs + r * 68 + n)       = make_float2(acc[mt][nt][0], acc[mt][nt][1]);
            *(float2*)(Gs + (r + 8) * 68 + n) = make_float2(acc[mt][nt][2], acc[mt][nt][3]);
        }
    __syncthreads();

    const float* __restrict__ Bias = LAYER ? g_Bias1 : g_Bias0;
    const float* __restrict__ Cp   = LAYER ? g_Cp1 : g_Cp0;
#pragma unroll
    for (int j = 0; j < 4; j++) {
        int p2 = t + 256 * j;           // 0..1023 -> (mb, hh)
        int mb = p2 >> 4, hh = p2 & 15;
        int b = m0 + mb, h = (n0 >> 2) + hh;
        float4 g4 = *(const float4*)(Gs + mb * 68 + hh * 4);
        float4 bi4 = *(const float4*)(Bias + n0 + hh * 4);
        float gi = g4.x + bi4.x, gf = g4.y + bi4.y, gg = g4.z + bi4.z, go = g4.w + bi4.w;
        float si = 1.0f / (1.0f + expf(-gi));
        float sf = 1.0f / (1.0f + expf(-gf));
        float so = 1.0f / (1.0f + expf(-go));
        float c2 = sf * Cp[b * HH + h] + si * tanhf(gg);
        float h2 = so * tanhf(c2);

        if (LAYER == 0) {
            g_H0[b * HH + h] = h2;
            g_C0[b * HH + h] = c2;
            __nv_bfloat16 hi_, lo_;
            bfsplit(h2, hi_, lo_);
            g_XH1hi[b * KTOT + h] = hi_;
            g_XH1lo[b * KTOT + h] = lo_;
        } else {
            int pp = pos[b];
            float h0 = g_H0[b * HH + h];
            float c0 = g_C0[b * HH + h];
            size_t base = (((size_t)(pp + 1) * BB + b) * HH + h) * 2;
            *(float2*)(hs_out + base) = make_float2(h0, h2);
            *(float2*)(cs_out + base) = make_float2(c0, c2);
            if (h == HH - 1) {
                int o = op[b];
                float2 hv, cv;
                if (o == 1) { hv = make_float2(h0, h2); cv = make_float2(c0, c2); }
                else {
                    size_t gi2 = (((size_t)(pp + o) * BB + b) * HH + (HH - 1)) * 2;
                    hv = *(const float2*)(hs + gi2);
                    cv = *(const float2*)(cs + gi2);
                }
                *(float2*)(out + b * 2) = hv;            // h_out (1,B,L)
                *(float2*)(out + BB * 2 + b * 2) = cv;   // c_out (1,B,L)
            }
        }
    }
}

// ---------------- final copy ----------------
#define FINAL_COPY_CTAS 592
__global__ void __launch_bounds__(256) k_copy(
        const float* __restrict__ hs, const float* __restrict__ cs,
        float* __restrict__ hs_out, float* __restrict__ cs_out,
        const int* __restrict__ pos, long row_start, long row_end) {
    int gwarp = blockIdx.x * 8 + (threadIdx.x >> 5);
    copy_rows(hs, cs, hs_out, cs_out, pos, row_start, row_end,
              gwarp, FINAL_COPY_CTAS * 8, threadIdx.x & 31);
}

// ---------------- launch ----------------
extern "C" void kernel_launch(void* const* d_in, const int* in_sizes, int n_in,
                              void* d_out, int out_size) {
    const float* x    = (const float*)d_in[0];
    const float* hs   = (const float*)d_in[1];
    const float* cs   = (const float*)d_in[2];
    const float* wih0 = (const float*)d_in[3];
    const float* whh0 = (const float*)d_in[4];
    const float* bih0 = (const float*)d_in[5];
    const float* bhh0 = (const float*)d_in[6];
    const float* wih1 = (const float*)d_in[7];
    const float* whh1 = (const float*)d_in[8];
    const float* bih1 = (const float*)d_in[9];
    const float* bhh1 = (const float*)d_in[10];
    const int*   op   = (const int*)d_in[11];
    const int*   pos  = (const int*)d_in[12];
    float* out = (float*)d_out;

    float* hs_out = out + 2 * BB * 2;
    float* cs_out = hs_out + STACKN;

    static int smem_set = 0;
    if (!smem_set) {
        cudaFuncSetAttribute(k_gemm<0>, cudaFuncAttributeMaxDynamicSharedMemorySize, SMEM_GEMM);
        cudaFuncSetAttribute(k_gemm<1>, cudaFuncAttributeMaxDynamicSharedMemorySize, SMEM_GEMM);
        smem_set = 1;
    }

    long r0 = 0;
    long r1 = r0 + R_PRO;
    long r2 = r1 + R_G0;
    long r3 = r2 + R_G1;

    k_prologue<<<BB + WPREP_CTAS + 1 + PRO_COPY_CTAS, 256>>>(
        x, hs, cs, wih0, whh0, bih0, bhh0, wih1, whh1, bih1, bhh1,
        pos, hs_out, cs_out, r0, r1);
    k_gemm<0><<<GEMM_CTAS + GEMM_COPY_CTAS, 256, SMEM_GEMM>>>(
        hs, cs, hs_out, cs_out, op, pos, out, r1, r2);
    k_gemm<1><<<GEMM_CTAS + GEMM_COPY_CTAS, 256, SMEM_GEMM>>>(
        hs, cs, hs_out, cs_out, op, pos, out, r2, r3);
    k_copy<<<FINAL_COPY_CTAS, 256>>>(hs, cs, hs_out, cs_out, pos, r3, ROWS_TOTAL);
}

// round 11
// speedup vs baseline: 1.4800x; 1.0313x over previous
#include <cuda_runtime.h>
#include <cuda_bf16.h>
#include <math.h>
#include <stdint.h>

#define BB 256
#define INF 256
#define HH 256
#define KTOT 512
#define NG 1024
#define NSTK 129
#define STACKN ((size_t)NSTK * BB * HH * 2)
#define ROWS_PER_STACK ((long)NSTK * BB)       // 33024
#define ROWS_TOTAL (2 * ROWS_PER_STACK)        // 66048

// ---------------- scratch ----------------
__device__ float g_Cp0[BB * HH], g_Cp1[BB * HH];
__device__ float g_H0[BB * HH], g_C0[BB * HH];
__device__ float g_Bias0[NG], g_Bias1[NG];     // gate-interleaved combined bias
__device__ __align__(16) __nv_bfloat16 g_XH0hi[BB * KTOT], g_XH0lo[BB * KTOT];
__device__ __align__(16) __nv_bfloat16 g_XH1hi[BB * KTOT], g_XH1lo[BB * KTOT];
__device__ __align__(16) __nv_bfloat16 g_W0hi[NG * KTOT], g_W0lo[NG * KTOT];   // [n'][k], n' = h*4+gate
__device__ __align__(16) __nv_bfloat16 g_W1hi[NG * KTOT], g_W1lo[NG * KTOT];

__device__ __forceinline__ uint32_t smem_u32(const void* p) {
    uint32_t a;
    asm("{ .reg .u64 t; cvta.to.shared.u64 t, %1; cvt.u32.u64 %0, t; }" : "=r"(a) : "l"(p));
    return a;
}
__device__ __forceinline__ void cp16(uint32_t saddr, const void* gaddr) {
    asm volatile("cp.async.cg.shared.global [%0], [%1], 16;" :: "r"(saddr), "l"(gaddr));
}
#define CP_COMMIT() asm volatile("cp.async.commit_group;" ::: "memory")
#define CP_WAIT(n)  asm volatile("cp.async.wait_group %0;" :: "n"(n) : "memory")

__device__ __forceinline__ void bfsplit(float v, __nv_bfloat16& hi, __nv_bfloat16& lo) {
    hi = __float2bfloat16(v);
    lo = __float2bfloat16(v - __bfloat162float(hi));
}

__device__ __forceinline__ void hmma(float* c, uint32_t a0, uint32_t a1, uint32_t a2, uint32_t a3,
                                     uint32_t b0, uint32_t b1) {
    asm volatile(
        "mma.sync.aligned.m16n8k16.row.col.f32.bf16.bf16.f32 "
        "{%0,%1,%2,%3}, {%4,%5,%6,%7}, {%8,%9}, {%0,%1,%2,%3};"
        : "+f"(c[0]), "+f"(c[1]), "+f"(c[2]), "+f"(c[3])
        : "r"(a0), "r"(a1), "r"(a2), "r"(a3), "r"(b0), "r"(b1));
}

// ---------------- full-stack copy (runs on forked stream, fully concurrent) ----------------
// Skips rows s == pos[b]+1 (gemm1 epilogue owns them) -> no ordering dependency.
#define COPY_CTAS 1184
__global__ void __launch_bounds__(256) k_copy(
        const float* __restrict__ hs, const float* __restrict__ cs,
        float* __restrict__ hs_out, float* __restrict__ cs_out,
        const int* __restrict__ pos) {
    int gwarp = blockIdx.x * 8 + (threadIdx.x >> 5);
    int lane = threadIdx.x & 31;
    const int nwarps = COPY_CTAS * 8;
    for (long r = gwarp; r < ROWS_TOTAL; r += nwarps) {
        long rs = r;
        const float* src;
        float* dst;
        if (rs < ROWS_PER_STACK) { src = hs; dst = hs_out; }
        else { rs -= ROWS_PER_STACK; src = cs; dst = cs_out; }
        int s = (int)(rs >> 8);
        int b = (int)(rs & 255);
        if (s == pos[b] + 1) continue;
        const float4* s4 = (const float4*)(src + rs * 512);
        float4* d4 = (float4*)(dst + rs * 512);
        float4 v0 = __ldcs(s4 + lane);
        float4 v1 = __ldcs(s4 + lane + 32);
        float4 v2 = __ldcs(s4 + lane + 64);
        float4 v3 = __ldcs(s4 + lane + 96);
        __stcs(d4 + lane, v0);
        __stcs(d4 + lane + 32, v1);
        __stcs(d4 + lane + 64, v2);
        __stcs(d4 + lane + 96, v3);
    }
}

// ---------------- prologue: gather + weight split (gate-interleaved) + bias ----------------
#define WPREP_CTAS 128
union BF8U { __nv_bfloat16 b[8]; uint4 u; };

__global__ void __launch_bounds__(256) k_prologue(
        const float* __restrict__ x, const float* __restrict__ hs, const float* __restrict__ cs,
        const float* __restrict__ wih0, const float* __restrict__ whh0,
        const float* __restrict__ bih0, const float* __restrict__ bhh0,
        const float* __restrict__ wih1, const float* __restrict__ whh1,
        const float* __restrict__ bih1, const float* __restrict__ bhh1,
        const int* __restrict__ pos) {
    int bid = blockIdx.x;
    int t = threadIdx.x;
    if (bid < BB) {
        int b = bid, h = t;
        int s = pos[b];
        size_t idx = (((size_t)s * BB + b) * HH + h) * 2;
        float2 hv = *(const float2*)(hs + idx);
        float2 cv = *(const float2*)(cs + idx);
        __nv_bfloat16 hi, lo;
        bfsplit(x[b * INF + h], hi, lo);
        g_XH0hi[b * KTOT + h] = hi; g_XH0lo[b * KTOT + h] = lo;
        bfsplit(hv.x, hi, lo);
        g_XH0hi[b * KTOT + INF + h] = hi; g_XH0lo[b * KTOT + INF + h] = lo;
        bfsplit(hv.y, hi, lo);
        g_XH1hi[b * KTOT + INF + h] = hi; g_XH1lo[b * KTOT + INF + h] = lo;
        g_Cp0[b * HH + h] = cv.x;
        g_Cp1[b * HH + h] = cv.y;
        return;
    }
    if (bid < BB + WPREP_CTAS) {
        // weight split into bf16 hi/lo; layout [n'][k], n' = h*4+gate, k = [wih | whh]
        int tid0 = (bid - BB) * 256 + t;
        for (int g = tid0; g < 2 * NG * 64; g += WPREP_CTAS * 256) {
            int layer = g >> 16;
            int rem = g & 65535;
            int np = rem >> 6;               // n' 0..1023
            int k8 = (rem & 63) * 8;
            int hid = np >> 2, gate = np & 3;
            int orign = gate * HH + hid;
            const float* wih = layer ? wih1 : wih0;
            const float* whh = layer ? whh1 : whh0;
            const float* srcp = (k8 < INF) ? (wih + (size_t)orign * INF + k8)
                                           : (whh + (size_t)orign * INF + (k8 - INF));
            float4 a = *(const float4*)srcp;
            float4 bq = *(const float4*)(srcp + 4);
            float v[8] = {a.x, a.y, a.z, a.w, bq.x, bq.y, bq.z, bq.w};
            BF8U uhi, ulo;
#pragma unroll
            for (int j = 0; j < 8; j++) bfsplit(v[j], uhi.b[j], ulo.b[j]);
            __nv_bfloat16* dhi = layer ? g_W1hi : g_W0hi;
            __nv_bfloat16* dlo = layer ? g_W1lo : g_W0lo;
            *(uint4*)(dhi + (size_t)np * KTOT + k8) = uhi.u;
            *(uint4*)(dlo + (size_t)np * KTOT + k8) = ulo.u;
        }
        return;
    }
    // combined bias in n'-space
#pragma unroll
    for (int e = 0; e < 8; e++) {
        int idx = e * 256 + t;
        int layer = idx >> 10;
        int np = idx & 1023;
        int hid = np >> 2, gate = np & 3;
        int orign = gate * HH + hid;
        float v = (layer ? bih1 : bih0)[orign] + (layer ? bhh1 : bhh0)[orign];
        (layer ? g_Bias1 : g_Bias0)[np] = v;
    }
}

// ---------------- fused HMMA GEMM + LSTM epilogue ----------------
// gates'[256, 1024] = XH[256,512] @ W'[1024,512]^T  (n' gate-interleaved)
// 64 CTAs: tile 64(m) x 64(n'), 8 warps (2m x 4n), warp tile 32x16.
// K chunks of 32, 4-stage cp.async pipeline. 3-term bf16 split.
#define GEMM_CTAS 64
#define APAD 40                          // bf16 row stride in smem
#define ARR_BYTES (64 * APAD * 2)        // 5120 per array
#define STAGE_BYTES (4 * ARR_BYTES)      // 20480 (AH, AL, BH, BL)
#define SMEM_GEMM (4 * STAGE_BYTES)      // 81920
#define OFF_AH(p) ((p) * STAGE_BYTES)
#define OFF_AL(p) ((p) * STAGE_BYTES + ARR_BYTES)
#define OFF_BH(p) ((p) * STAGE_BYTES + 2 * ARR_BYTES)
#define OFF_BL(p) ((p) * STAGE_BYTES + 3 * ARR_BYTES)
#define NCHUNK 16

template <int LAYER>
__global__ void __launch_bounds__(256) k_gemm(
        const float* __restrict__ hs, const float* __restrict__ cs,
        float* __restrict__ hs_out, float* __restrict__ cs_out,
        const int* __restrict__ op, const int* __restrict__ pos,
        float* __restrict__ out) {
    const int bid = blockIdx.x;
    const int t = threadIdx.x;

    extern __shared__ char smem[];
    const uint32_t sb = smem_u32(smem);

    const __nv_bfloat16* __restrict__ Ahi = LAYER ? g_XH1hi : g_XH0hi;
    const __nv_bfloat16* __restrict__ Alo = LAYER ? g_XH1lo : g_XH0lo;
    const __nv_bfloat16* __restrict__ Bhi = LAYER ? g_W1hi : g_W0hi;
    const __nv_bfloat16* __restrict__ Blo = LAYER ? g_W1lo : g_W0lo;

    const int m0 = (bid & 3) * 64;      // 4 m tiles
    const int n0 = (bid >> 2) * 64;     // 16 n' tiles
    const int wid = t >> 5, lane = t & 31;
    const int wm = (wid & 1) * 32;      // warp m offset
    const int wn = (wid >> 1) * 16;     // warp n offset
    const int lr = lane >> 2;           // 0..7
    const int lc = (lane & 3) * 2;      // 0,2,4,6

    // cp.async per-thread assignment: 64 rows x 4 uint4-chunks, 1 per thread per array
    const int arow = t >> 2, aj = t & 3;

    float acc[2][2][4];
#pragma unroll
    for (int i = 0; i < 2; i++)
#pragma unroll
        for (int j = 0; j < 2; j++)
#pragma unroll
            for (int q = 0; q < 4; q++) acc[i][j][q] = 0.f;

    auto load_chunk = [&](int c, int p) {
        int kc = c * 32;
        cp16(sb + OFF_AH(p) + arow * (APAD * 2) + aj * 16,
             Ahi + (size_t)(m0 + arow) * KTOT + kc + aj * 8);
        cp16(sb + OFF_AL(p) + arow * (APAD * 2) + aj * 16,
             Alo + (size_t)(m0 + arow) * KTOT + kc + aj * 8);
        cp16(sb + OFF_BH(p) + arow * (APAD * 2) + aj * 16,
             Bhi + (size_t)(n0 + arow) * KTOT + kc + aj * 8);
        cp16(sb + OFF_BL(p) + arow * (APAD * 2) + aj * 16,
             Blo + (size_t)(n0 + arow) * KTOT + kc + aj * 8);
    };

    load_chunk(0, 0); CP_COMMIT();
    load_chunk(1, 1); CP_COMMIT();
    load_chunk(2, 2); CP_COMMIT();

#pragma unroll 1
    for (int c = 0; c < NCHUNK; c++) {
        int p = c & 3;
        if (c < NCHUNK - 2)      { CP_WAIT(2); }
        else if (c == NCHUNK - 2){ CP_WAIT(1); }
        else                     { CP_WAIT(0); }
        __syncthreads();
        if (c + 3 < NCHUNK) { load_chunk(c + 3, (c + 3) & 3); CP_COMMIT(); }

        const __nv_bfloat16* ah = (const __nv_bfloat16*)(smem + OFF_AH(p));
        const __nv_bfloat16* al = (const __nv_bfloat16*)(smem + OFF_AL(p));
        const __nv_bfloat16* bh = (const __nv_bfloat16*)(smem + OFF_BH(p));
        const __nv_bfloat16* bl = (const __nv_bfloat16*)(smem + OFF_BL(p));

#pragma unroll
        for (int k0 = 0; k0 < 32; k0 += 16) {
            uint32_t AH[2][4], AL[2][4], BH[2][2], BL[2][2];
#pragma unroll
            for (int mt = 0; mt < 2; mt++) {
                int r = wm + mt * 16 + lr;
                int cc = k0 + lc;
                AH[mt][0] = *(const uint32_t*)(ah + r * APAD + cc);
                AH[mt][1] = *(const uint32_t*)(ah + (r + 8) * APAD + cc);
                AH[mt][2] = *(const uint32_t*)(ah + r * APAD + cc + 8);
                AH[mt][3] = *(const uint32_t*)(ah + (r + 8) * APAD + cc + 8);
                AL[mt][0] = *(const uint32_t*)(al + r * APAD + cc);
                AL[mt][1] = *(const uint32_t*)(al + (r + 8) * APAD + cc);
                AL[mt][2] = *(const uint32_t*)(al + r * APAD + cc + 8);
                AL[mt][3] = *(const uint32_t*)(al + (r + 8) * APAD + cc + 8);
            }
#pragma unroll
            for (int nt = 0; nt < 2; nt++) {
                int n = wn + nt * 8 + lr;
                int cc = k0 + lc;
                BH[nt][0] = *(const uint32_t*)(bh + n * APAD + cc);
                BH[nt][1] = *(const uint32_t*)(bh + n * APAD + cc + 8);
                BL[nt][0] = *(const uint32_t*)(bl + n * APAD + cc);
                BL[nt][1] = *(const uint32_t*)(bl + n * APAD + cc + 8);
            }
#pragma unroll
            for (int mt = 0; mt < 2; mt++)
#pragma unroll
                for (int nt = 0; nt < 2; nt++) {
                    hmma(acc[mt][nt], AH[mt][0], AH[mt][1], AH[mt][2], AH[mt][3], BH[nt][0], BH[nt][1]);
                    hmma(acc[mt][nt], AH[mt][0], AH[mt][1], AH[mt][2], AH[mt][3], BL[nt][0], BL[nt][1]);
                    hmma(acc[mt][nt], AL[mt][0], AL[mt][1], AL[mt][2], AL[mt][3], BH[nt][0], BH[nt][1]);
                }
        }
        __syncthreads();
    }

    // ---- fused LSTM epilogue ----
    float* Gs = (float*)smem;   // 64 x 68 fp32 gates (pre-bias), reuses stage smem
    __syncthreads();
#pragma unroll
    for (int mt = 0; mt < 2; mt++)
#pragma unroll
        for (int nt = 0; nt < 2; nt++) {
            int r = wm + mt * 16 + lr;
            int n = wn + nt * 8 + lc;
            *(float2*)(Gs + r * 68 + n)       = make_float2(acc[mt][nt][0], acc[mt][nt][1]);
            *(float2*)(Gs + (r + 8) * 68 + n) = make_float2(acc[mt][nt][2], acc[mt][nt][3]);
        }
    __syncthreads();

    const float* __restrict__ Bias = LAYER ? g_Bias1 : g_Bias0;
    const float* __restrict__ Cp   = LAYER ? g_Cp1 : g_Cp0;
#pragma unroll
    for (int j = 0; j < 4; j++) {
        int p2 = t + 256 * j;           // 0..1023 -> (mb, hh)
        int mb = p2 >> 4, hh = p2 & 15;
        int b = m0 + mb, h = (n0 >> 2) + hh;
        float4 g4 = *(const float4*)(Gs + mb * 68 + hh * 4);
        float4 bi4 = *(const float4*)(Bias + n0 + hh * 4);
        float gi = g4.x + bi4.x, gf = g4.y + bi4.y, gg = g4.z + bi4.z, go = g4.w + bi4.w;
        float si = 1.0f / (1.0f + expf(-gi));
        float sf = 1.0f / (1.0f + expf(-gf));
        float so = 1.0f / (1.0f + expf(-go));
        float c2 = sf * Cp[b * HH + h] + si * tanhf(gg);
        float h2 = so * tanhf(c2);

        if (LAYER == 0) {
            g_H0[b * HH + h] = h2;
            g_C0[b * HH + h] = c2;
            __nv_bfloat16 hi_, lo_;
            bfsplit(h2, hi_, lo_);
            g_XH1hi[b * KTOT + h] = hi_;
            g_XH1lo[b * KTOT + h] = lo_;
        } else {
            int pp = pos[b];
            float h0 = g_H0[b * HH + h];
            float c0 = g_C0[b * HH + h];
            size_t base = (((size_t)(pp + 1) * BB + b) * HH + h) * 2;
            *(float2*)(hs_out + base) = make_float2(h0, h2);
            *(float2*)(cs_out + base) = make_float2(c0, c2);
            if (h == HH - 1) {
                int o = op[b];
                float2 hv, cv;
                if (o == 1) { hv = make_float2(h0, h2); cv = make_float2(c0, c2); }
                else {
                    size_t gi2 = (((size_t)(pp + o) * BB + b) * HH + (HH - 1)) * 2;
                    hv = *(const float2*)(hs + gi2);
                    cv = *(const float2*)(cs + gi2);
                }
                *(float2*)(out + b * 2) = hv;            // h_out (1,B,L)
                *(float2*)(out + BB * 2 + b * 2) = cv;   // c_out (1,B,L)
            }
        }
    }
}

// ---------------- launch ----------------
extern "C" void kernel_launch(void* const* d_in, const int* in_sizes, int n_in,
                              void* d_out, int out_size) {
    const float* x    = (const float*)d_in[0];
    const float* hs   = (const float*)d_in[1];
    const float* cs   = (const float*)d_in[2];
    const float* wih0 = (const float*)d_in[3];
    const float* whh0 = (const float*)d_in[4];
    const float* bih0 = (const float*)d_in[5];
    const float* bhh0 = (const float*)d_in[6];
    const float* wih1 = (const float*)d_in[7];
    const float* whh1 = (const float*)d_in[8];
    const float* bih1 = (const float*)d_in[9];
    const float* bhh1 = (const float*)d_in[10];
    const int*   op   = (const int*)d_in[11];
    const int*   pos  = (const int*)d_in[12];
    float* out = (float*)d_out;

    float* hs_out = out + 2 * BB * 2;
    float* cs_out = hs_out + STACKN;

    static cudaStream_t s2 = nullptr;
    static cudaEvent_t evFork = nullptr, evJoin = nullptr;
    if (!s2) {
        cudaStreamCreate(&s2);
        cudaEventCreateWithFlags(&evFork, cudaEventDisableTiming);
        cudaEventCreateWithFlags(&evJoin, cudaEventDisableTiming);
        cudaFuncSetAttribute(k_gemm<0>, cudaFuncAttributeMaxDynamicSharedMemorySize, SMEM_GEMM);
        cudaFuncSetAttribute(k_gemm<1>, cudaFuncAttributeMaxDynamicSharedMemorySize, SMEM_GEMM);
    }

    // fork: bulk copy runs concurrently with the compute chain
    cudaEventRecord(evFork, 0);
    cudaStreamWaitEvent(s2, evFork, 0);
    k_copy<<<COPY_CTAS, 256, 0, s2>>>(hs, cs, hs_out, cs_out, pos);
    cudaEventRecord(evJoin, s2);

    // compute chain on the main (capture) stream
    k_prologue<<<BB + WPREP_CTAS + 1, 256>>>(
        x, hs, cs, wih0, whh0, bih0, bhh0, wih1, whh1, bih1, bhh1, pos);
    k_gemm<0><<<GEMM_CTAS, 256, SMEM_GEMM>>>(hs, cs, hs_out, cs_out, op, pos, out);
    k_gemm<1><<<GEMM_CTAS, 256, SMEM_GEMM>>>(hs, cs, hs_out, cs_out, op, pos, out);

    // join
    cudaStreamWaitEvent(0, evJoin, 0);
}